// round 3
// baseline (speedup 1.0000x reference)
#include <cuda_runtime.h>
#include <cuda_bf16.h>
#include <cstdint>

#define DI __device__ __forceinline__

// ---------------- constants ----------------
constexpr int DIM = 128;
constexpr int ROW_FLOATS = DIM * DIM;     // 16384 floats per sample
constexpr int ROW_BYTES = DIM * 2;        // 256 B per bf16 tile row
constexpr int TILE_BYTES = DIM * ROW_BYTES;  // 32 KB

constexpr int OFF_WB_HI = 0;
constexpr int OFF_WB_LO = 1 * TILE_BYTES;
constexpr int OFF_WA_HI = 2 * TILE_BYTES;
constexpr int OFF_WA_LO = 3 * TILE_BYTES;
constexpr int OFF_X_HI  = 4 * TILE_BYTES;   // X for GEMM1, reused as T for GEMM2
constexpr int OFF_X_LO  = 5 * TILE_BYTES;
constexpr int SMEM_BYTES = 6 * TILE_BYTES;  // 192 KB

// ---------------- helpers ----------------
DI uint32_t smem_u32(const void* p) {
    uint32_t a;
    asm("{ .reg .u64 t; cvta.to.shared.u64 t, %1; cvt.u32.u64 %0, t; }" : "=r"(a) : "l"(p));
    return a;
}

// Byte offset of (row, col[bf16]) in a swizzled 128x128 bf16 tile.
// Row = 256 B = 16 chunks of 16 B; chunk index is XORed with (row & 7)
// so 8 consecutive rows hit 8 distinct bank groups (conflict-free ldmatrix).
DI uint32_t toff(int row, int col) {
    return (uint32_t)(row * ROW_BYTES) + ((((col >> 3) ^ (row & 7)) << 4)) +
           ((col & 7) << 1);
}

DI void ldsm4(uint32_t& r0, uint32_t& r1, uint32_t& r2, uint32_t& r3, uint32_t a) {
    asm volatile("ldmatrix.sync.aligned.m8n8.x4.shared.b16 {%0,%1,%2,%3}, [%4];"
                 : "=r"(r0), "=r"(r1), "=r"(r2), "=r"(r3) : "r"(a));
}

DI void mma16816(float* d, const uint32_t* a, uint32_t b0, uint32_t b1) {
    asm volatile(
        "mma.sync.aligned.m16n8k16.row.col.f32.bf16.bf16.f32 "
        "{%0,%1,%2,%3}, {%4,%5,%6,%7}, {%8,%9}, {%0,%1,%2,%3};"
        : "+f"(d[0]), "+f"(d[1]), "+f"(d[2]), "+f"(d[3])
        : "r"(a[0]), "r"(a[1]), "r"(a[2]), "r"(a[3]), "r"(b0), "r"(b1));
}

// fp32 -> (hi bf16, lo bf16) split; pack two lanes into one 32-bit word each.
DI void split2(float a, float b, uint32_t& h, uint32_t& l) {
    __nv_bfloat16 ha = __float2bfloat16(a);
    __nv_bfloat16 hb = __float2bfloat16(b);
    __nv_bfloat16 la = __float2bfloat16(a - __bfloat162float(ha));
    __nv_bfloat16 lb = __float2bfloat16(b - __bfloat162float(hb));
    h = (uint32_t)__bfloat16_as_ushort(ha) | ((uint32_t)__bfloat16_as_ushort(hb) << 16);
    l = (uint32_t)__bfloat16_as_ushort(la) | ((uint32_t)__bfloat16_as_ushort(lb) << 16);
}

// Load 128x128 fp32 row-major from gmem, split hi/lo bf16, store swizzled tiles.
DI void cvt_tile(const float* __restrict__ src, char* smem, int off_hi, int off_lo,
                 int tid) {
#pragma unroll
    for (int it = 0; it < 8; it++) {
        int g = tid + it * 256;              // 2048 chunks total
        int row = g >> 4;
        int col = (g & 15) << 3;             // 8 bf16 per chunk
        const float4* p = reinterpret_cast<const float4*>(src + row * DIM + col);
        float4 v0 = p[0];
        float4 v1 = p[1];
        uint4 hi, lo;
        split2(v0.x, v0.y, hi.x, lo.x);
        split2(v0.z, v0.w, hi.y, lo.y);
        split2(v1.x, v1.y, hi.z, lo.z);
        split2(v1.z, v1.w, hi.w, lo.w);
        uint32_t o = toff(row, col);
        *reinterpret_cast<uint4*>(smem + off_hi + o) = hi;
        *reinterpret_cast<uint4*>(smem + off_lo + o) = lo;
    }
}

// One 128x128x128 fp32-accurate GEMM, warp tile m32 x n64.
// acc[mt][nt][4] += (Ah+Al)*(Bh+Bl) minus the lo*lo term.
DI void gemm3(float acc[2][8][4], uint32_t a_hi, uint32_t a_lo,
              uint32_t b_hi, uint32_t b_lo, int m0, int n0, int lane) {
    const int a_row_off = lane & 15;          // A: lanes 0-15 rows, 16-31 k+8
    const int a_col_off = (lane >> 4) << 3;
    const int b_row_off = (lane & 7) + ((lane >> 4) << 3);  // B: n rows
    const int b_col_off = ((lane >> 3) & 1) << 3;

#pragma unroll
    for (int k = 0; k < 8; k++) {
        const int kb = k << 4;
        uint32_t Ah[2][4], Al[2][4], Bh[4][4], Bl[4][4];
#pragma unroll
        for (int mt = 0; mt < 2; mt++) {
            uint32_t o = toff(m0 + mt * 16 + a_row_off, kb + a_col_off);
            ldsm4(Ah[mt][0], Ah[mt][1], Ah[mt][2], Ah[mt][3], a_hi + o);
            ldsm4(Al[mt][0], Al[mt][1], Al[mt][2], Al[mt][3], a_lo + o);
        }
#pragma unroll
        for (int p = 0; p < 4; p++) {
            uint32_t o = toff(n0 + p * 16 + b_row_off, kb + b_col_off);
            ldsm4(Bh[p][0], Bh[p][1], Bh[p][2], Bh[p][3], b_hi + o);
            ldsm4(Bl[p][0], Bl[p][1], Bl[p][2], Bl[p][3], b_lo + o);
        }
#pragma unroll
        for (int mt = 0; mt < 2; mt++) {
#pragma unroll
            for (int nt = 0; nt < 8; nt++) {
                const int p = nt >> 1, q = (nt & 1) << 1;
                mma16816(acc[mt][nt], Ah[mt], Bh[p][q], Bh[p][q + 1]);
                mma16816(acc[mt][nt], Al[mt], Bh[p][q], Bh[p][q + 1]);
                mma16816(acc[mt][nt], Ah[mt], Bl[p][q], Bl[p][q + 1]);
            }
        }
    }
}

DI void zero_acc(float acc[2][8][4]) {
#pragma unroll
    for (int mt = 0; mt < 2; mt++)
#pragma unroll
        for (int nt = 0; nt < 8; nt++)
#pragma unroll
            for (int i = 0; i < 4; i++) acc[mt][nt][i] = 0.f;
}

// ---------------- kernel ----------------
__global__ void __launch_bounds__(256, 1)
krone_kernel(const float* __restrict__ x, const float* __restrict__ wa,
             const float* __restrict__ wb, const float* __restrict__ bias,
             float* __restrict__ out, int n_samples) {
    extern __shared__ char smem[];
    const uint32_t sb = smem_u32(smem);
    const int tid = threadIdx.x;
    const int wid = tid >> 5;
    const int lane = tid & 31;
    const int m0 = (wid & 3) * 32;     // warp output tile: rows [m0, m0+32)
    const int n0 = (wid >> 2) * 64;    // cols [n0, n0+64)

    // Convert weights once (persistent kernel)
    cvt_tile(wb, smem, OFF_WB_HI, OFF_WB_LO, tid);
    cvt_tile(wa, smem, OFF_WA_HI, OFF_WA_LO, tid);

    const int er = lane >> 2;          // acc fragment row within m16 tile
    const int ec = (lane & 3) << 1;    // acc fragment col pair within n8 tile

    float acc[2][8][4];

    for (int n = blockIdx.x; n < n_samples; n += gridDim.x) {
        // ---- load + split x into X tiles ----
        cvt_tile(x + (size_t)n * ROW_FLOATS, smem, OFF_X_HI, OFF_X_LO, tid);
        __syncthreads();

        // ---- GEMM1: D1[o_b, j] = Wb . X^T ----
        zero_acc(acc);
        gemm3(acc, sb + OFF_WB_HI, sb + OFF_WB_LO, sb + OFF_X_HI, sb + OFF_X_LO,
              m0, n0, lane);
        __syncthreads();   // everyone done reading X before overwrite with T

        // ---- store D1 into T tiles [o_b][j] (GEMM2's B operand layout) ----
#pragma unroll
        for (int mt = 0; mt < 2; mt++) {
#pragma unroll
            for (int nt = 0; nt < 8; nt++) {
                const int col = n0 + nt * 8 + ec;
                uint32_t h, l;
                split2(acc[mt][nt][0], acc[mt][nt][1], h, l);
                uint32_t o = toff(m0 + mt * 16 + er, col);
                *reinterpret_cast<uint32_t*>(smem + OFF_X_HI + o) = h;
                *reinterpret_cast<uint32_t*>(smem + OFF_X_LO + o) = l;
                split2(acc[mt][nt][2], acc[mt][nt][3], h, l);
                o = toff(m0 + mt * 16 + er + 8, col);
                *reinterpret_cast<uint32_t*>(smem + OFF_X_HI + o) = h;
                *reinterpret_cast<uint32_t*>(smem + OFF_X_LO + o) = l;
            }
        }
        __syncthreads();

        // ---- GEMM2: D2[o_a, o_b] = Wa . T^T ----
        zero_acc(acc);
        gemm3(acc, sb + OFF_WA_HI, sb + OFF_WA_LO, sb + OFF_X_HI, sb + OFF_X_LO,
              m0, n0, lane);

        // ---- epilogue: out[n, o_a*128 + o_b] = D2 + bias ----
        float* outn = out + (size_t)n * ROW_FLOATS;
#pragma unroll
        for (int mt = 0; mt < 2; mt++) {
#pragma unroll
            for (int nt = 0; nt < 8; nt++) {
                const int col = n0 + nt * 8 + ec;
                int row = m0 + mt * 16 + er;
                float2 bv = *reinterpret_cast<const float2*>(bias + row * DIM + col);
                float2 o0 = {acc[mt][nt][0] + bv.x, acc[mt][nt][1] + bv.y};
                *reinterpret_cast<float2*>(outn + row * DIM + col) = o0;
                row += 8;
                bv = *reinterpret_cast<const float2*>(bias + row * DIM + col);
                float2 o1 = {acc[mt][nt][2] + bv.x, acc[mt][nt][3] + bv.y};
                *reinterpret_cast<float2*>(outn + row * DIM + col) = o1;
            }
        }
        __syncthreads();   // all warps done reading T before next sample's cvt
    }
}

// ---------------- launcher ----------------
extern "C" void kernel_launch(void* const* d_in, const int* in_sizes, int n_in,
                              void* d_out, int out_size) {
    const float* x    = (const float*)d_in[0];
    const float* wa   = (const float*)d_in[1];
    const float* wb   = (const float*)d_in[2];
    const float* bias = (const float*)d_in[3];
    float* out = (float*)d_out;
    int n_samples = in_sizes[0] / ROW_FLOATS;

    cudaFuncSetAttribute(krone_kernel, cudaFuncAttributeMaxDynamicSharedMemorySize,
                         SMEM_BYTES);
    int grid = n_samples < 148 ? n_samples : 148;
    krone_kernel<<<grid, 256, SMEM_BYTES>>>(x, wa, wb, bias, out, n_samples);
}

// round 4
// speedup vs baseline: 1.1074x; 1.1074x over previous
#include <cuda_runtime.h>
#include <cuda_bf16.h>
#include <cstdint>

#define DI __device__ __forceinline__

// ---------------- constants ----------------
constexpr int DIM = 128;
constexpr int ROW_FLOATS = DIM * DIM;     // 16384 floats per sample
constexpr int ROW_BYTES = DIM * 2;        // 256 B per bf16 tile row
constexpr int TILE_BYTES = DIM * ROW_BYTES;  // 32 KB
constexpr int NT = 512;                   // 16 warps

constexpr int OFF_WB_HI = 0;
constexpr int OFF_WB_LO = 1 * TILE_BYTES;
constexpr int OFF_WA_HI = 2 * TILE_BYTES;
constexpr int OFF_WA_LO = 3 * TILE_BYTES;
constexpr int OFF_X_HI  = 4 * TILE_BYTES;   // X for GEMM1, reused as T for GEMM2
constexpr int OFF_X_LO  = 5 * TILE_BYTES;
constexpr int SMEM_BYTES = 6 * TILE_BYTES;  // 192 KB

// ---------------- helpers ----------------
DI uint32_t smem_u32(const void* p) {
    uint32_t a;
    asm("{ .reg .u64 t; cvta.to.shared.u64 t, %1; cvt.u32.u64 %0, t; }" : "=r"(a) : "l"(p));
    return a;
}

// Byte offset of (row, col[bf16]) in a swizzled 128x128 bf16 tile.
// Row = 256 B = 16 chunks of 16 B; chunk index XORed with (row & 7) so
// 8 consecutive rows hit 8 distinct bank groups (conflict-free ldmatrix).
DI uint32_t toff(int row, int col) {
    return (uint32_t)(row * ROW_BYTES) + ((((col >> 3) ^ (row & 7)) << 4)) +
           ((col & 7) << 1);
}

DI void ldsm4(uint32_t& r0, uint32_t& r1, uint32_t& r2, uint32_t& r3, uint32_t a) {
    asm volatile("ldmatrix.sync.aligned.m8n8.x4.shared.b16 {%0,%1,%2,%3}, [%4];"
                 : "=r"(r0), "=r"(r1), "=r"(r2), "=r"(r3) : "r"(a));
}

DI void mma16816(float* d, const uint32_t* a, uint32_t b0, uint32_t b1) {
    asm volatile(
        "mma.sync.aligned.m16n8k16.row.col.f32.bf16.bf16.f32 "
        "{%0,%1,%2,%3}, {%4,%5,%6,%7}, {%8,%9}, {%0,%1,%2,%3};"
        : "+f"(d[0]), "+f"(d[1]), "+f"(d[2]), "+f"(d[3])
        : "r"(a[0]), "r"(a[1]), "r"(a[2]), "r"(a[3]), "r"(b0), "r"(b1));
}

// fp32 -> (hi bf16, lo bf16) split; pack two lanes into one 32-bit word each.
DI void split2(float a, float b, uint32_t& h, uint32_t& l) {
    __nv_bfloat16 ha = __float2bfloat16(a);
    __nv_bfloat16 hb = __float2bfloat16(b);
    __nv_bfloat16 la = __float2bfloat16(a - __bfloat162float(ha));
    __nv_bfloat16 lb = __float2bfloat16(b - __bfloat162float(hb));
    h = (uint32_t)__bfloat16_as_ushort(ha) | ((uint32_t)__bfloat16_as_ushort(hb) << 16);
    l = (uint32_t)__bfloat16_as_ushort(la) | ((uint32_t)__bfloat16_as_ushort(lb) << 16);
}

// Load 128x128 fp32 row-major from gmem, split hi/lo bf16, store swizzled tiles.
DI void cvt_tile(const float* __restrict__ src, char* smem, int off_hi, int off_lo,
                 int tid) {
#pragma unroll
    for (int it = 0; it < 2048 / NT; it++) {
        int g = tid + it * NT;               // 2048 16B-chunks total
        int row = g >> 4;
        int col = (g & 15) << 3;             // 8 bf16 per chunk
        const float4* p = reinterpret_cast<const float4*>(src + row * DIM + col);
        float4 v0 = p[0];
        float4 v1 = p[1];
        uint4 hi, lo;
        split2(v0.x, v0.y, hi.x, lo.x);
        split2(v0.z, v0.w, hi.y, lo.y);
        split2(v1.x, v1.y, hi.z, lo.z);
        split2(v1.z, v1.w, hi.w, lo.w);
        uint32_t o = toff(row, col);
        *reinterpret_cast<uint4*>(smem + off_hi + o) = hi;
        *reinterpret_cast<uint4*>(smem + off_lo + o) = lo;
    }
}

// One 128x128x128 fp32-accurate GEMM, warp tile m32 x n32.
// acc += Ah*Bh + Al*Bh + Ah*Bl  (lo*lo term dropped, O(2^-18)).
DI void gemm3(float acc[2][4][4], uint32_t a_hi, uint32_t a_lo,
              uint32_t b_hi, uint32_t b_lo, int m0, int n0, int lane) {
    const int a_row_off = lane & 15;          // A: lanes 0-15 rows, 16-31 k+8
    const int a_col_off = (lane >> 4) << 3;
    const int b_row_off = (lane & 7) + ((lane >> 4) << 3);  // B: n rows
    const int b_col_off = ((lane >> 3) & 1) << 3;

#pragma unroll
    for (int k = 0; k < 8; k++) {
        const int kb = k << 4;
        uint32_t Ah[2][4], Al[2][4], Bh[2][4], Bl[2][4];
#pragma unroll
        for (int mt = 0; mt < 2; mt++) {
            uint32_t o = toff(m0 + mt * 16 + a_row_off, kb + a_col_off);
            ldsm4(Ah[mt][0], Ah[mt][1], Ah[mt][2], Ah[mt][3], a_hi + o);
            ldsm4(Al[mt][0], Al[mt][1], Al[mt][2], Al[mt][3], a_lo + o);
        }
#pragma unroll
        for (int p = 0; p < 2; p++) {
            uint32_t o = toff(n0 + p * 16 + b_row_off, kb + b_col_off);
            ldsm4(Bh[p][0], Bh[p][1], Bh[p][2], Bh[p][3], b_hi + o);
            ldsm4(Bl[p][0], Bl[p][1], Bl[p][2], Bl[p][3], b_lo + o);
        }
#pragma unroll
        for (int mt = 0; mt < 2; mt++) {
#pragma unroll
            for (int nt = 0; nt < 4; nt++) {
                const int p = nt >> 1, q = (nt & 1) << 1;
                mma16816(acc[mt][nt], Ah[mt], Bh[p][q], Bh[p][q + 1]);
                mma16816(acc[mt][nt], Al[mt], Bh[p][q], Bh[p][q + 1]);
                mma16816(acc[mt][nt], Ah[mt], Bl[p][q], Bl[p][q + 1]);
            }
        }
    }
}

DI void zero_acc(float acc[2][4][4]) {
#pragma unroll
    for (int mt = 0; mt < 2; mt++)
#pragma unroll
        for (int nt = 0; nt < 4; nt++)
#pragma unroll
            for (int i = 0; i < 4; i++) acc[mt][nt][i] = 0.f;
}

// ---------------- kernel ----------------
__global__ void __launch_bounds__(NT, 1)
krone_kernel(const float* __restrict__ x, const float* __restrict__ wa,
             const float* __restrict__ wb, const float* __restrict__ bias,
             float* __restrict__ out, int n_samples) {
    extern __shared__ char smem[];
    const uint32_t sb = smem_u32(smem);
    const int tid = threadIdx.x;
    const int wid = tid >> 5;
    const int lane = tid & 31;
    const int m0 = (wid & 3) * 32;     // warp output tile: rows [m0, m0+32)
    const int n0 = (wid >> 2) * 32;    // cols [n0, n0+32)

    // Convert weights once (persistent kernel)
    cvt_tile(wb, smem, OFF_WB_HI, OFF_WB_LO, tid);
    cvt_tile(wa, smem, OFF_WA_HI, OFF_WA_LO, tid);

    const int er = lane >> 2;          // acc fragment row within m16 tile
    const int ec = (lane & 3) << 1;    // acc fragment col pair within n8 tile

    float acc[2][4][4];

    for (int n = blockIdx.x; n < n_samples; n += gridDim.x) {
        // ---- load + split x into X tiles ----
        cvt_tile(x + (size_t)n * ROW_FLOATS, smem, OFF_X_HI, OFF_X_LO, tid);
        __syncthreads();

        // ---- GEMM1: D1[o_b, j] = Wb . X^T ----
        zero_acc(acc);
        gemm3(acc, sb + OFF_WB_HI, sb + OFF_WB_LO, sb + OFF_X_HI, sb + OFF_X_LO,
              m0, n0, lane);
        __syncthreads();   // everyone done reading X before overwrite with T

        // ---- store D1 into T tiles [o_b][j] (GEMM2's B operand layout) ----
#pragma unroll
        for (int mt = 0; mt < 2; mt++) {
#pragma unroll
            for (int nt = 0; nt < 4; nt++) {
                const int col = n0 + nt * 8 + ec;
                uint32_t h, l;
                split2(acc[mt][nt][0], acc[mt][nt][1], h, l);
                uint32_t o = toff(m0 + mt * 16 + er, col);
                *reinterpret_cast<uint32_t*>(smem + OFF_X_HI + o) = h;
                *reinterpret_cast<uint32_t*>(smem + OFF_X_LO + o) = l;
                split2(acc[mt][nt][2], acc[mt][nt][3], h, l);
                o = toff(m0 + mt * 16 + er + 8, col);
                *reinterpret_cast<uint32_t*>(smem + OFF_X_HI + o) = h;
                *reinterpret_cast<uint32_t*>(smem + OFF_X_LO + o) = l;
            }
        }
        __syncthreads();

        // ---- GEMM2: D2[o_a, o_b] = Wa . T^T ----
        zero_acc(acc);
        gemm3(acc, sb + OFF_WA_HI, sb + OFF_WA_LO, sb + OFF_X_HI, sb + OFF_X_LO,
              m0, n0, lane);

        // ---- epilogue: out[n, o_a*128 + o_b] = D2 + bias ----
        float* outn = out + (size_t)n * ROW_FLOATS;
#pragma unroll
        for (int mt = 0; mt < 2; mt++) {
#pragma unroll
            for (int nt = 0; nt < 4; nt++) {
                const int col = n0 + nt * 8 + ec;
                int row = m0 + mt * 16 + er;
                float2 bv = *reinterpret_cast<const float2*>(bias + row * DIM + col);
                float2 o0 = {acc[mt][nt][0] + bv.x, acc[mt][nt][1] + bv.y};
                *reinterpret_cast<float2*>(outn + row * DIM + col) = o0;
                row += 8;
                bv = *reinterpret_cast<const float2*>(bias + row * DIM + col);
                float2 o1 = {acc[mt][nt][2] + bv.x, acc[mt][nt][3] + bv.y};
                *reinterpret_cast<float2*>(outn + row * DIM + col) = o1;
            }
        }
        __syncthreads();   // all warps done reading T before next sample's cvt
    }
}

// ---------------- launcher ----------------
extern "C" void kernel_launch(void* const* d_in, const int* in_sizes, int n_in,
                              void* d_out, int out_size) {
    const float* x    = (const float*)d_in[0];
    const float* wa   = (const float*)d_in[1];
    const float* wb   = (const float*)d_in[2];
    const float* bias = (const float*)d_in[3];
    float* out = (float*)d_out;
    int n_samples = in_sizes[0] / ROW_FLOATS;

    cudaFuncSetAttribute(krone_kernel, cudaFuncAttributeMaxDynamicSharedMemorySize,
                         SMEM_BYTES);
    int grid = n_samples < 148 ? n_samples : 148;
    krone_kernel<<<grid, NT, SMEM_BYTES>>>(x, wa, wb, bias, out, n_samples);
}